// round 2
// baseline (speedup 1.0000x reference)
#include <cuda_runtime.h>
#include <mma.h>

using namespace nvcuda;

#define DIMX   512
#define SEQ    4096
#define BATCH  4
#define NROWS  (BATCH * SEQ)     // 16384
#define HIDN   1024              // HID
#define HID2   2048              // 2*HID
#define QKD    128
#define OUTD   8

// ---------------------------------------------------------------------------
// Scratch (device globals; allocation in kernel_launch is forbidden)
// ---------------------------------------------------------------------------
__device__ float g_normed[(size_t)NROWS * DIMX];           // 32 MB
__device__ float g_q[(size_t)NROWS * QKD];                 // 8 MB
__device__ float g_k[(size_t)NROWS * QKD];                 // 8 MB
__device__ float g_v[(size_t)NROWS * HIDN];                // 64 MB
__device__ float g_gate[(size_t)NROWS * HIDN];             // 64 MB
__device__ float g_A[(size_t)BATCH * SEQ * SEQ];           // 268 MB
__device__ float g_V[(size_t)NROWS * HIDN];                // 64 MB

// ---------------------------------------------------------------------------
// Kernel 1: LayerNorm. One warp per row of 512.
// ---------------------------------------------------------------------------
__global__ __launch_bounds__(256) void ln_kernel(
    const float* __restrict__ x, const float* __restrict__ g,
    const float* __restrict__ b)
{
    int row  = blockIdx.x * 8 + (threadIdx.x >> 5);
    int lane = threadIdx.x & 31;
    const float4* xr = reinterpret_cast<const float4*>(x + (size_t)row * DIMX);

    float4 v[4];
    float s = 0.f, s2 = 0.f;
#pragma unroll
    for (int w = 0; w < 4; w++) {
        v[w] = xr[lane + 32 * w];
        s  += v[w].x + v[w].y + v[w].z + v[w].w;
        s2 += v[w].x * v[w].x + v[w].y * v[w].y + v[w].z * v[w].z + v[w].w * v[w].w;
    }
#pragma unroll
    for (int off = 16; off; off >>= 1) {
        s  += __shfl_xor_sync(0xFFFFFFFFu, s,  off);
        s2 += __shfl_xor_sync(0xFFFFFFFFu, s2, off);
    }
    float mu   = s  * (1.0f / DIMX);
    float var  = s2 * (1.0f / DIMX) - mu * mu;
    float rstd = rsqrtf(var + 1e-5f);

    float4* nr = reinterpret_cast<float4*>(g_normed + (size_t)row * DIMX);
    const float4* gg = reinterpret_cast<const float4*>(g);
    const float4* bb = reinterpret_cast<const float4*>(b);
#pragma unroll
    for (int w = 0; w < 4; w++) {
        int f = lane + 32 * w;
        float4 gv = gg[f], bv = bb[f], o;
        o.x = (v[w].x - mu) * rstd * gv.x + bv.x;
        o.y = (v[w].y - mu) * rstd * gv.y + bv.y;
        o.z = (v[w].z - mu) * rstd * gv.z + bv.z;
        o.w = (v[w].w - mu) * rstd * gv.w + bv.w;
        nr[f] = o;
    }
}

// ---------------------------------------------------------------------------
// tf32 wmma tile config: BM=64, BN=64, BK=32, 128 threads (4 warps, 2x2),
// each warp computes a 32x32 region (2x2 fragments of 16x16).
// ---------------------------------------------------------------------------
#define AS_LD 40   // 64 x 40 floats  (pad: 160B row, 16B multiple)
#define BS_LD 72   // 32 x 72 floats
#define CS_LD 72   // 64 x 72 floats

__device__ __forceinline__ float silu(float x) {
    return x / (1.0f + expf(-x));
}

// MODE 0: C = silu(normed @ Wh + bh)  -> split into g_v / g_gate
// MODE 1: Z = silu(normed @ Wqk + bqk); q=Z*gamma0+beta0; k=Z*gamma1+beta1
template<int MODE>
__global__ __launch_bounds__(128) void proj_kernel(
    const float* __restrict__ B, const float* __restrict__ bias,
    const float* __restrict__ gamma, const float* __restrict__ beta, int Ntot)
{
    __shared__ __align__(16) float As[64 * AS_LD];
    __shared__ __align__(16) float Bs[32 * BS_LD];
    __shared__ __align__(16) float Cs[64 * CS_LD];

    int tid  = threadIdx.x;
    int warp = tid >> 5;
    int wm = warp & 1, wn = warp >> 1;
    int row0 = blockIdx.y * 64;
    int col0 = blockIdx.x * 64;

    wmma::fragment<wmma::accumulator, 16, 16, 8, float> acc[2][2];
#pragma unroll
    for (int i = 0; i < 2; i++)
#pragma unroll
        for (int j = 0; j < 2; j++) wmma::fill_fragment(acc[i][j], 0.0f);

    for (int kt = 0; kt < DIMX; kt += 32) {
#pragma unroll
        for (int i = tid; i < 512; i += 128) {        // A tile 64x32
            int r = i >> 3, c = (i & 7) << 2;
            float4 t = *reinterpret_cast<const float4*>(
                g_normed + (size_t)(row0 + r) * DIMX + kt + c);
            *reinterpret_cast<float4*>(As + r * AS_LD + c) = t;
        }
#pragma unroll
        for (int i = tid; i < 512; i += 128) {        // B tile 32x64
            int r = i >> 4, c = (i & 15) << 2;
            float4 t = *reinterpret_cast<const float4*>(
                B + (size_t)(kt + r) * Ntot + col0 + c);
            *reinterpret_cast<float4*>(Bs + r * BS_LD + c) = t;
        }
        __syncthreads();
#pragma unroll
        for (int kk = 0; kk < 32; kk += 8) {
            wmma::fragment<wmma::matrix_a, 16, 16, 8, wmma::precision::tf32, wmma::row_major> af[2];
            wmma::fragment<wmma::matrix_b, 16, 16, 8, wmma::precision::tf32, wmma::row_major> bf[2];
#pragma unroll
            for (int i = 0; i < 2; i++) {
                wmma::load_matrix_sync(af[i], As + (wm * 32 + i * 16) * AS_LD + kk, AS_LD);
#pragma unroll
                for (int e = 0; e < af[i].num_elements; e++)
                    af[i].x[e] = wmma::__float_to_tf32(af[i].x[e]);
                wmma::load_matrix_sync(bf[i], Bs + kk * BS_LD + wn * 32 + i * 16, BS_LD);
#pragma unroll
                for (int e = 0; e < bf[i].num_elements; e++)
                    bf[i].x[e] = wmma::__float_to_tf32(bf[i].x[e]);
            }
#pragma unroll
            for (int mi = 0; mi < 2; mi++)
#pragma unroll
                for (int ni = 0; ni < 2; ni++)
                    wmma::mma_sync(acc[mi][ni], af[mi], bf[ni], acc[mi][ni]);
        }
        __syncthreads();
    }

#pragma unroll
    for (int mi = 0; mi < 2; mi++)
#pragma unroll
        for (int ni = 0; ni < 2; ni++)
            wmma::store_matrix_sync(Cs + (wm * 32 + mi * 16) * CS_LD + wn * 32 + ni * 16,
                                    acc[mi][ni], CS_LD, wmma::mem_row_major);
    __syncthreads();

    for (int i = tid; i < 64 * 64; i += 128) {
        int r = i >> 6, c = i & 63;
        int gr = row0 + r, gc = col0 + c;
        float val = Cs[r * CS_LD + c] + bias[gc];
        float s = silu(val);
        if (MODE == 0) {
            if (gc < HIDN) g_v[(size_t)gr * HIDN + gc] = s;
            else           g_gate[(size_t)gr * HIDN + gc - HIDN] = s;
        } else {
            g_q[(size_t)gr * QKD + gc] = s * gamma[gc]       + beta[gc];
            g_k[(size_t)gr * QKD + gc] = s * gamma[QKD + gc] + beta[QKD + gc];
        }
    }
}

// ---------------------------------------------------------------------------
// Kernel 4: A = relu(q @ k^T / SEQ)^2 per batch.  M=N=4096, K=128.
// ---------------------------------------------------------------------------
__global__ __launch_bounds__(128) void attn_s_kernel()
{
    __shared__ __align__(16) float As[64 * AS_LD];
    __shared__ __align__(16) float Ks[64 * AS_LD];   // 64 k-rows x 32 dims

    int tid  = threadIdx.x;
    int warp = tid >> 5;
    int wm = warp & 1, wn = warp >> 1;
    int b  = blockIdx.z;
    int i0 = blockIdx.y * 64;
    int j0 = blockIdx.x * 64;
    const float* qb = g_q + (size_t)b * SEQ * QKD;
    const float* kb = g_k + (size_t)b * SEQ * QKD;

    wmma::fragment<wmma::accumulator, 16, 16, 8, float> acc[2][2];
#pragma unroll
    for (int i = 0; i < 2; i++)
#pragma unroll
        for (int j = 0; j < 2; j++) wmma::fill_fragment(acc[i][j], 0.0f);

    for (int kt = 0; kt < QKD; kt += 32) {
#pragma unroll
        for (int i = tid; i < 512; i += 128) {
            int r = i >> 3, c = (i & 7) << 2;
            *reinterpret_cast<float4*>(As + r * AS_LD + c) =
                *reinterpret_cast<const float4*>(qb + (size_t)(i0 + r) * QKD + kt + c);
            *reinterpret_cast<float4*>(Ks + r * AS_LD + c) =
                *reinterpret_cast<const float4*>(kb + (size_t)(j0 + r) * QKD + kt + c);
        }
        __syncthreads();
#pragma unroll
        for (int kk = 0; kk < 32; kk += 8) {
            wmma::fragment<wmma::matrix_a, 16, 16, 8, wmma::precision::tf32, wmma::row_major> af[2];
            wmma::fragment<wmma::matrix_b, 16, 16, 8, wmma::precision::tf32, wmma::col_major> bf[2];
#pragma unroll
            for (int i = 0; i < 2; i++) {
                wmma::load_matrix_sync(af[i], As + (wm * 32 + i * 16) * AS_LD + kk, AS_LD);
#pragma unroll
                for (int e = 0; e < af[i].num_elements; e++)
                    af[i].x[e] = wmma::__float_to_tf32(af[i].x[e]);
                // col-major view: element (k, n) at Ks[(col)(AS_LD) + k]
                wmma::load_matrix_sync(bf[i], Ks + (wn * 32 + i * 16) * AS_LD + kk, AS_LD);
#pragma unroll
                for (int e = 0; e < bf[i].num_elements; e++)
                    bf[i].x[e] = wmma::__float_to_tf32(bf[i].x[e]);
            }
#pragma unroll
            for (int mi = 0; mi < 2; mi++)
#pragma unroll
                for (int ni = 0; ni < 2; ni++)
                    wmma::mma_sync(acc[mi][ni], af[mi], bf[ni], acc[mi][ni]);
        }
        __syncthreads();
    }

    // Elementwise epilogue directly on fragments: relu(s/SEQ)^2
    const float inv_n = 1.0f / (float)SEQ;
    float* Ab = g_A + (size_t)b * SEQ * SEQ;
#pragma unroll
    for (int mi = 0; mi < 2; mi++)
#pragma unroll
        for (int ni = 0; ni < 2; ni++) {
#pragma unroll
            for (int e = 0; e < acc[mi][ni].num_elements; e++) {
                float sv = acc[mi][ni].x[e] * inv_n;
                sv = fmaxf(sv, 0.0f);
                acc[mi][ni].x[e] = sv * sv;
            }
            wmma::store_matrix_sync(
                Ab + (size_t)(i0 + wm * 32 + mi * 16) * SEQ + j0 + wn * 32 + ni * 16,
                acc[mi][ni], SEQ, wmma::mem_row_major);
        }
}

// ---------------------------------------------------------------------------
// Kernel 5: V = (A @ v) * gate per batch.  M=4096, N=1024, K=4096.
// ---------------------------------------------------------------------------
__global__ __launch_bounds__(128) void attn_v_kernel()
{
    __shared__ __align__(16) float As[64 * AS_LD];
    __shared__ __align__(16) float Bs[32 * BS_LD];
    __shared__ __align__(16) float Cs[64 * CS_LD];

    int tid  = threadIdx.x;
    int warp = tid >> 5;
    int wm = warp & 1, wn = warp >> 1;
    int b  = blockIdx.z;
    int i0 = blockIdx.y * 64;
    int n0 = blockIdx.x * 64;
    const float* Ab = g_A + (size_t)b * SEQ * SEQ;
    const float* vb = g_v + (size_t)b * SEQ * HIDN;

    wmma::fragment<wmma::accumulator, 16, 16, 8, float> acc[2][2];
#pragma unroll
    for (int i = 0; i < 2; i++)
#pragma unroll
        for (int j = 0; j < 2; j++) wmma::fill_fragment(acc[i][j], 0.0f);

    for (int kt = 0; kt < SEQ; kt += 32) {
#pragma unroll
        for (int i = tid; i < 512; i += 128) {      // A tile 64x32
            int r = i >> 3, c = (i & 7) << 2;
            *reinterpret_cast<float4*>(As + r * AS_LD + c) =
                *reinterpret_cast<const float4*>(Ab + (size_t)(i0 + r) * SEQ + kt + c);
        }
#pragma unroll
        for (int i = tid; i < 512; i += 128) {      // v tile 32x64
            int r = i >> 4, c = (i & 15) << 2;
            *reinterpret_cast<float4*>(Bs + r * BS_LD + c) =
                *reinterpret_cast<const float4*>(vb + (size_t)(kt + r) * HIDN + n0 + c);
        }
        __syncthreads();
#pragma unroll
        for (int kk = 0; kk < 32; kk += 8) {
            wmma::fragment<wmma::matrix_a, 16, 16, 8, wmma::precision::tf32, wmma::row_major> af[2];
            wmma::fragment<wmma::matrix_b, 16, 16, 8, wmma::precision::tf32, wmma::row_major> bf[2];
#pragma unroll
            for (int i = 0; i < 2; i++) {
                wmma::load_matrix_sync(af[i], As + (wm * 32 + i * 16) * AS_LD + kk, AS_LD);
#pragma unroll
                for (int e = 0; e < af[i].num_elements; e++)
                    af[i].x[e] = wmma::__float_to_tf32(af[i].x[e]);
                wmma::load_matrix_sync(bf[i], Bs + kk * BS_LD + wn * 32 + i * 16, BS_LD);
#pragma unroll
                for (int e = 0; e < bf[i].num_elements; e++)
                    bf[i].x[e] = wmma::__float_to_tf32(bf[i].x[e]);
            }
#pragma unroll
            for (int mi = 0; mi < 2; mi++)
#pragma unroll
                for (int ni = 0; ni < 2; ni++)
                    wmma::mma_sync(acc[mi][ni], af[mi], bf[ni], acc[mi][ni]);
        }
        __syncthreads();
    }

#pragma unroll
    for (int mi = 0; mi < 2; mi++)
#pragma unroll
        for (int ni = 0; ni < 2; ni++)
            wmma::store_matrix_sync(Cs + (wm * 32 + mi * 16) * CS_LD + wn * 32 + ni * 16,
                                    acc[mi][ni], CS_LD, wmma::mem_row_major);
    __syncthreads();

    for (int i = tid; i < 64 * 64; i += 128) {
        int r = i >> 6, c = i & 63;
        size_t grow = (size_t)(b * SEQ + i0 + r);
        size_t idx  = grow * HIDN + n0 + c;
        g_V[idx] = Cs[r * CS_LD + c] * g_gate[idx];
    }
}

// ---------------------------------------------------------------------------
// Kernel 6: out = V @ Wo + bo.  One warp per row, K=1024, N=8.
// ---------------------------------------------------------------------------
__global__ __launch_bounds__(256) void out_kernel(
    const float* __restrict__ Wo, const float* __restrict__ bo,
    float* __restrict__ out)
{
    int row  = blockIdx.x * 8 + (threadIdx.x >> 5);
    int lane = threadIdx.x & 31;
    const float* Vr = g_V + (size_t)row * HIDN;

    float acc[OUTD];
#pragma unroll
    for (int o = 0; o < OUTD; o++) acc[o] = 0.0f;

    for (int k = lane; k < HIDN; k += 32) {
        float vv = Vr[k];
        const float* w = Wo + (size_t)k * OUTD;
#pragma unroll
        for (int o = 0; o < OUTD; o++) acc[o] += vv * w[o];
    }
#pragma unroll
    for (int o = 0; o < OUTD; o++)
#pragma unroll
        for (int off = 16; off; off >>= 1)
            acc[o] += __shfl_xor_sync(0xFFFFFFFFu, acc[o], off);

    if (lane == 0) {
#pragma unroll
        for (int o = 0; o < OUTD; o++)
            out[(size_t)row * OUTD + o] = acc[o] + bo[o];
    }
}

// ---------------------------------------------------------------------------
// Launch
// ---------------------------------------------------------------------------
extern "C" void kernel_launch(void* const* d_in, const int* in_sizes, int n_in,
                              void* d_out, int out_size)
{
    const float* x     = (const float*)d_in[0];
    const float* ln_g  = (const float*)d_in[1];
    const float* ln_b  = (const float*)d_in[2];
    const float* Wh    = (const float*)d_in[3];
    const float* bh    = (const float*)d_in[4];
    const float* Wqk   = (const float*)d_in[5];
    const float* bqk   = (const float*)d_in[6];
    const float* gamma = (const float*)d_in[7];
    const float* beta  = (const float*)d_in[8];
    const float* Wo    = (const float*)d_in[9];
    const float* bo    = (const float*)d_in[10];
    float* out = (float*)d_out;

    ln_kernel<<<NROWS / 8, 256>>>(x, ln_g, ln_b);
    proj_kernel<0><<<dim3(HID2 / 64, NROWS / 64), 128>>>(Wh, bh, nullptr, nullptr, HID2);
    proj_kernel<1><<<dim3(QKD / 64, NROWS / 64), 128>>>(Wqk, bqk, gamma, beta, QKD);
    attn_s_kernel<<<dim3(SEQ / 64, SEQ / 64, BATCH), 128>>>();
    attn_v_kernel<<<dim3(HIDN / 64, SEQ / 64, BATCH), 128>>>();
    out_kernel<<<NROWS / 8, 256>>>(Wo, bo, out);
}

// round 4
// speedup vs baseline: 1.0344x; 1.0344x over previous
#include <cstdint>
#include <cuda_runtime.h>
#include <mma.h>

using namespace nvcuda;

#define DIMX   512
#define SEQ    4096
#define BATCH  4
#define NROWS  (BATCH * SEQ)     // 16384
#define HIDN   1024              // HID
#define HID2   2048              // 2*HID
#define QKD    128
#define OUTD   8

// ---------------------------------------------------------------------------
// Scratch (device globals; allocation in kernel_launch is forbidden)
// ---------------------------------------------------------------------------
__device__ float g_normed[(size_t)NROWS * DIMX];           // 32 MB
__device__ float g_q[(size_t)NROWS * QKD];                 // 8 MB
__device__ float g_k[(size_t)NROWS * QKD];                 // 8 MB
__device__ float g_v[(size_t)NROWS * HIDN];                // 64 MB
__device__ float g_gate[(size_t)NROWS * HIDN];             // 64 MB
__device__ float g_A[(size_t)BATCH * SEQ * SEQ];           // 268 MB
__device__ float g_V[(size_t)NROWS * HIDN];                // 64 MB

// ---------------------------------------------------------------------------
// cp.async helpers
// ---------------------------------------------------------------------------
__device__ __forceinline__ void cpa16(float* sdst, const float* gsrc) {
    unsigned int sa = (unsigned int)__cvta_generic_to_shared(sdst);
    asm volatile("cp.async.cg.shared.global [%0], [%1], 16;\n" :: "r"(sa), "l"(gsrc));
}
#define CP_COMMIT() asm volatile("cp.async.commit_group;\n" ::: "memory")
#define CP_WAIT0()  asm volatile("cp.async.wait_group 0;\n" ::: "memory")

__device__ __forceinline__ float silu(float x) {
    return x / (1.0f + expf(-x));
}

// Smem leading dims (floats; all multiples of 4 for 16B alignment)
#define AS_LD 36    // A tiles: 128 x 32 (+4 pad)
#define BS_LD 132   // B tiles: 32 x 128 (+4 pad)
#define CS_LD 132   // C staging: 128 x 128 (+4 pad)
#define KS_LD 136   // attn_s tiles: 128 x 128 (+8 pad)

#define GEMM_SMEM_BYTES  ((2*128*AS_LD + 2*32*BS_LD) * 4)   // 70656 (Cs aliases: 128*CS_LD*4=67584)
#define ATTNS_SMEM_BYTES (2 * 128 * KS_LD * 4)              // 139264

// ---------------------------------------------------------------------------
// Kernel 1: LayerNorm. One warp per row of 512.
// ---------------------------------------------------------------------------
__global__ __launch_bounds__(256) void ln_kernel(
    const float* __restrict__ x, const float* __restrict__ g,
    const float* __restrict__ b)
{
    int row  = blockIdx.x * 8 + (threadIdx.x >> 5);
    int lane = threadIdx.x & 31;
    const float4* xr = reinterpret_cast<const float4*>(x + (size_t)row * DIMX);

    float4 v[4];
    float s = 0.f, s2 = 0.f;
#pragma unroll
    for (int w = 0; w < 4; w++) {
        v[w] = xr[lane + 32 * w];
        s  += v[w].x + v[w].y + v[w].z + v[w].w;
        s2 += v[w].x * v[w].x + v[w].y * v[w].y + v[w].z * v[w].z + v[w].w * v[w].w;
    }
#pragma unroll
    for (int off = 16; off; off >>= 1) {
        s  += __shfl_xor_sync(0xFFFFFFFFu, s,  off);
        s2 += __shfl_xor_sync(0xFFFFFFFFu, s2, off);
    }
    float mu   = s  * (1.0f / DIMX);
    float var  = s2 * (1.0f / DIMX) - mu * mu;
    float rstd = rsqrtf(var + 1e-5f);

    float4* nr = reinterpret_cast<float4*>(g_normed + (size_t)row * DIMX);
    const float4* gg = reinterpret_cast<const float4*>(g);
    const float4* bb = reinterpret_cast<const float4*>(b);
#pragma unroll
    for (int w = 0; w < 4; w++) {
        int f = lane + 32 * w;
        float4 gv = gg[f], bv = bb[f], o;
        o.x = (v[w].x - mu) * rstd * gv.x + bv.x;
        o.y = (v[w].y - mu) * rstd * gv.y + bv.y;
        o.z = (v[w].z - mu) * rstd * gv.z + bv.z;
        o.w = (v[w].w - mu) * rstd * gv.w + bv.w;
        nr[f] = o;
    }
}

// ---------------------------------------------------------------------------
// Fragment compute core: 8 warps as 4m x 2n; warp tile 32 x 64 (acc[2][4]).
// ---------------------------------------------------------------------------
using FragA = wmma::fragment<wmma::matrix_a, 16, 16, 8, wmma::precision::tf32, wmma::row_major>;
using FragBr = wmma::fragment<wmma::matrix_b, 16, 16, 8, wmma::precision::tf32, wmma::row_major>;
using FragBc = wmma::fragment<wmma::matrix_b, 16, 16, 8, wmma::precision::tf32, wmma::col_major>;
using FragC = wmma::fragment<wmma::accumulator, 16, 16, 8, float>;

__device__ __forceinline__ void mma_step_rowB(
    FragC (&acc)[2][4], const float* As, const float* Bs, int wm, int wn)
{
#pragma unroll
    for (int kk = 0; kk < 32; kk += 8) {
        FragA af[2];
        FragBr bf[4];
#pragma unroll
        for (int i = 0; i < 2; i++) {
            wmma::load_matrix_sync(af[i], As + (wm * 32 + i * 16) * AS_LD + kk, AS_LD);
#pragma unroll
            for (int e = 0; e < af[i].num_elements; e++)
                af[i].x[e] = wmma::__float_to_tf32(af[i].x[e]);
        }
#pragma unroll
        for (int j = 0; j < 4; j++) {
            wmma::load_matrix_sync(bf[j], Bs + kk * BS_LD + wn * 64 + j * 16, BS_LD);
#pragma unroll
            for (int e = 0; e < bf[j].num_elements; e++)
                bf[j].x[e] = wmma::__float_to_tf32(bf[j].x[e]);
        }
#pragma unroll
        for (int mi = 0; mi < 2; mi++)
#pragma unroll
            for (int nj = 0; nj < 4; nj++)
                wmma::mma_sync(acc[mi][nj], af[mi], bf[nj], acc[mi][nj]);
    }
}

// ---------------------------------------------------------------------------
// proj kernels: C(128x128 tile) = act(A @ B + bias)
// MODE 0: silu -> split g_v / g_gate.  MODE 1: silu*gamma+beta -> g_q / g_k.
// Double-buffered cp.async pipeline over K.
// ---------------------------------------------------------------------------
template<int MODE>
__global__ __launch_bounds__(256) void proj_kernel(
    const float* __restrict__ B, const float* __restrict__ bias,
    const float* __restrict__ gamma, const float* __restrict__ beta, int Ntot)
{
    extern __shared__ float sm[];
    float* Asb[2] = { sm, sm + 128 * AS_LD };
    float* Bsb[2] = { sm + 2 * 128 * AS_LD, sm + 2 * 128 * AS_LD + 32 * BS_LD };
    float* Cs = sm;   // alias (used only after pipeline drains)

    int tid  = threadIdx.x;
    int warp = tid >> 5;
    int wm = warp >> 1, wn = warp & 1;
    int row0 = blockIdx.y * 128;
    int col0 = blockIdx.x * 128;

    FragC acc[2][4];
#pragma unroll
    for (int i = 0; i < 2; i++)
#pragma unroll
        for (int j = 0; j < 4; j++) wmma::fill_fragment(acc[i][j], 0.0f);

    auto load_tiles = [&](int buf, int kt) {
#pragma unroll
        for (int r4 = 0; r4 < 4; r4++) {            // A: 128x32 = 1024 float4
            int i = tid + 256 * r4;
            int r = i >> 3, c = (i & 7) << 2;
            cpa16(Asb[buf] + r * AS_LD + c,
                  g_normed + (size_t)(row0 + r) * DIMX + kt + c);
        }
#pragma unroll
        for (int r4 = 0; r4 < 4; r4++) {            // B: 32x128 = 1024 float4
            int i = tid + 256 * r4;
            int r = i >> 5, c = (i & 31) << 2;
            cpa16(Bsb[buf] + r * BS_LD + c,
                  B + (size_t)(kt + r) * Ntot + col0 + c);
        }
        CP_COMMIT();
    };

    const int KT = DIMX / 32;   // 16
    load_tiles(0, 0);
    for (int kt = 0; kt < KT; kt++) {
        CP_WAIT0();
        __syncthreads();
        if (kt + 1 < KT) load_tiles((kt + 1) & 1, (kt + 1) * 32);
        mma_step_rowB(acc, Asb[kt & 1], Bsb[kt & 1], wm, wn);
    }
    __syncthreads();   // all warps done reading As/Bs before Cs alias write

#pragma unroll
    for (int mi = 0; mi < 2; mi++)
#pragma unroll
        for (int nj = 0; nj < 4; nj++)
            wmma::store_matrix_sync(Cs + (wm * 32 + mi * 16) * CS_LD + wn * 64 + nj * 16,
                                    acc[mi][nj], CS_LD, wmma::mem_row_major);
    __syncthreads();

    for (int i4 = tid * 4; i4 < 128 * 128; i4 += 256 * 4) {
        int r = i4 >> 7, c = i4 & 127;
        int gr = row0 + r, gc = col0 + c;
        float4 cv = *reinterpret_cast<float4*>(Cs + r * CS_LD + c);
        float4 bi = *reinterpret_cast<const float4*>(bias + gc);
        float4 o;
        o.x = silu(cv.x + bi.x); o.y = silu(cv.y + bi.y);
        o.z = silu(cv.z + bi.z); o.w = silu(cv.w + bi.w);
        if (MODE == 0) {
            if (gc < HIDN)
                *reinterpret_cast<float4*>(g_v + (size_t)gr * HIDN + gc) = o;
            else
                *reinterpret_cast<float4*>(g_gate + (size_t)gr * HIDN + gc - HIDN) = o;
        } else {
            float4 g0 = *reinterpret_cast<const float4*>(gamma + gc);
            float4 b0 = *reinterpret_cast<const float4*>(beta + gc);
            float4 g1 = *reinterpret_cast<const float4*>(gamma + QKD + gc);
            float4 b1 = *reinterpret_cast<const float4*>(beta + QKD + gc);
            float4 qv, kv;
            qv.x = o.x * g0.x + b0.x; qv.y = o.y * g0.y + b0.y;
            qv.z = o.z * g0.z + b0.z; qv.w = o.w * g0.w + b0.w;
            kv.x = o.x * g1.x + b1.x; kv.y = o.y * g1.y + b1.y;
            kv.z = o.z * g1.z + b1.z; kv.w = o.w * g1.w + b1.w;
            *reinterpret_cast<float4*>(g_q + (size_t)gr * QKD + gc) = qv;
            *reinterpret_cast<float4*>(g_k + (size_t)gr * QKD + gc) = kv;
        }
    }
}

// ---------------------------------------------------------------------------
// attn_s: A = relu(q @ k^T / SEQ)^2.  Tile 128x128, full K=128 resident.
// ---------------------------------------------------------------------------
__global__ __launch_bounds__(256) void attn_s_kernel()
{
    extern __shared__ float sm[];
    float* Qs = sm;                   // 128 x KS_LD
    float* Ks = sm + 128 * KS_LD;     // 128 x KS_LD

    int tid  = threadIdx.x;
    int warp = tid >> 5;
    int wm = warp >> 1, wn = warp & 1;
    int b  = blockIdx.z;
    int i0 = blockIdx.y * 128;
    int j0 = blockIdx.x * 128;
    const float* qb = g_q + (size_t)b * SEQ * QKD;
    const float* kb = g_k + (size_t)b * SEQ * QKD;

    // Load full 128x128 q and k tiles (16 float4 per thread per tile)
#pragma unroll
    for (int r4 = 0; r4 < 16; r4++) {
        int i = tid + 256 * r4;
        int r = i >> 5, c = (i & 31) << 2;
        cpa16(Qs + r * KS_LD + c, qb + (size_t)(i0 + r) * QKD + c);
        cpa16(Ks + r * KS_LD + c, kb + (size_t)(j0 + r) * QKD + c);
    }
    CP_COMMIT();

    FragC acc[2][4];
#pragma unroll
    for (int i = 0; i < 2; i++)
#pragma unroll
        for (int j = 0; j < 4; j++) wmma::fill_fragment(acc[i][j], 0.0f);

    CP_WAIT0();
    __syncthreads();

#pragma unroll
    for (int kk = 0; kk < QKD; kk += 8) {
        FragA af[2];
        FragBc bf[4];
#pragma unroll
        for (int i = 0; i < 2; i++) {
            wmma::load_matrix_sync(af[i], Qs + (wm * 32 + i * 16) * KS_LD + kk, KS_LD);
#pragma unroll
            for (int e = 0; e < af[i].num_elements; e++)
                af[i].x[e] = wmma::__float_to_tf32(af[i].x[e]);
        }
#pragma unroll
        for (int j = 0; j < 4; j++) {
            // col-major view over Ks: element (k, n) at Ks[n*KS_LD + k]
            wmma::load_matrix_sync(bf[j], Ks + (wn * 64 + j * 16) * KS_LD + kk, KS_LD);
#pragma unroll
            for (int e = 0; e < bf[j].num_elements; e++)
                bf[j].x[e] = wmma::__float_to_tf32(bf[j].x[e]);
        }
#pragma unroll
        for (int mi = 0; mi < 2; mi++)
#pragma unroll
            for (int nj = 0; nj < 4; nj++)
                wmma::mma_sync(acc[mi][nj], af[mi], bf[nj], acc[mi][nj]);
    }

    // Epilogue on fragments: relu(s/SEQ)^2, direct global store
    const float inv_n = 1.0f / (float)SEQ;
    float* Ab = g_A + (size_t)b * SEQ * SEQ;
#pragma unroll
    for (int mi = 0; mi < 2; mi++)
#pragma unroll
        for (int nj = 0; nj < 4; nj++) {
#pragma unroll
            for (int e = 0; e < acc[mi][nj].num_elements; e++) {
                float sv = fmaxf(acc[mi][nj].x[e] * inv_n, 0.0f);
                acc[mi][nj].x[e] = sv * sv;
            }
            wmma::store_matrix_sync(
                Ab + (size_t)(i0 + wm * 32 + mi * 16) * SEQ + j0 + wn * 64 + nj * 16,
                acc[mi][nj], SEQ, wmma::mem_row_major);
        }
}

// ---------------------------------------------------------------------------
// attn_v: V = (A @ v) * gate.  M=4096, N=1024, K=4096 per batch.
// Double-buffered cp.async pipeline, 128x128x32 tiles.
// ---------------------------------------------------------------------------
__global__ __launch_bounds__(256) void attn_v_kernel()
{
    extern __shared__ float sm[];
    float* Asb[2] = { sm, sm + 128 * AS_LD };
    float* Bsb[2] = { sm + 2 * 128 * AS_LD, sm + 2 * 128 * AS_LD + 32 * BS_LD };
    float* Cs = sm;

    int tid  = threadIdx.x;
    int warp = tid >> 5;
    int wm = warp >> 1, wn = warp & 1;
    int b  = blockIdx.z;
    int i0 = blockIdx.y * 128;
    int n0 = blockIdx.x * 128;
    const float* Ab = g_A + (size_t)b * SEQ * SEQ;
    const float* vb = g_v + (size_t)b * SEQ * HIDN;

    FragC acc[2][4];
#pragma unroll
    for (int i = 0; i < 2; i++)
#pragma unroll
        for (int j = 0; j < 4; j++) wmma::fill_fragment(acc[i][j], 0.0f);

    auto load_tiles = [&](int buf, int kt) {
#pragma unroll
        for (int r4 = 0; r4 < 4; r4++) {
            int i = tid + 256 * r4;
            int r = i >> 3, c = (i & 7) << 2;
            cpa16(Asb[buf] + r * AS_LD + c,
                  Ab + (size_t)(i0 + r) * SEQ + kt + c);
        }
#pragma unroll
        for (int r4 = 0; r4 < 4; r4++) {
            int i = tid + 256 * r4;
            int r = i >> 5, c = (i & 31) << 2;
            cpa16(Bsb[buf] + r * BS_LD + c,
                  vb + (size_t)(kt + r) * HIDN + n0 + c);
        }
        CP_COMMIT();
    };

    const int KT = SEQ / 32;   // 128
    load_tiles(0, 0);
    for (int kt = 0; kt < KT; kt++) {
        CP_WAIT0();
        __syncthreads();
        if (kt + 1 < KT) load_tiles((kt + 1) & 1, (kt + 1) * 32);
        mma_step_rowB(acc, Asb[kt & 1], Bsb[kt & 1], wm, wn);
    }
    __syncthreads();

#pragma unroll
    for (int mi = 0; mi < 2; mi++)
#pragma unroll
        for (int nj = 0; nj < 4; nj++)
            wmma::store_matrix_sync(Cs + (wm * 32 + mi * 16) * CS_LD + wn * 64 + nj * 16,
                                    acc[mi][nj], CS_LD, wmma::mem_row_major);
    __syncthreads();

    for (int i4 = tid * 4; i4 < 128 * 128; i4 += 256 * 4) {
        int r = i4 >> 7, c = i4 & 127;
        size_t idx = (size_t)(b * SEQ + i0 + r) * HIDN + n0 + c;
        float4 cv = *reinterpret_cast<float4*>(Cs + r * CS_LD + c);
        float4 gt = *reinterpret_cast<const float4*>(g_gate + idx);
        float4 o;
        o.x = cv.x * gt.x; o.y = cv.y * gt.y;
        o.z = cv.z * gt.z; o.w = cv.w * gt.w;
        *reinterpret_cast<float4*>(g_V + idx) = o;
    }
}

// ---------------------------------------------------------------------------
// out = V @ Wo + bo.  One warp per row, K=1024, N=8.
// ---------------------------------------------------------------------------
__global__ __launch_bounds__(256) void out_kernel(
    const float* __restrict__ Wo, const float* __restrict__ bo,
    float* __restrict__ out)
{
    int row  = blockIdx.x * 8 + (threadIdx.x >> 5);
    int lane = threadIdx.x & 31;
    const float* Vr = g_V + (size_t)row * HIDN;

    float acc[OUTD];
#pragma unroll
    for (int o = 0; o < OUTD; o++) acc[o] = 0.0f;

#pragma unroll 4
    for (int k = lane; k < HIDN; k += 32) {
        float vv = Vr[k];
        const float* w = Wo + (size_t)k * OUTD;
#pragma unroll
        for (int o = 0; o < OUTD; o++) acc[o] += vv * w[o];
    }
#pragma unroll
    for (int o = 0; o < OUTD; o++)
#pragma unroll
        for (int off = 16; off; off >>= 1)
            acc[o] += __shfl_xor_sync(0xFFFFFFFFu, acc[o], off);

    if (lane == 0) {
#pragma unroll
        for (int o = 0; o < OUTD; o++)
            out[(size_t)row * OUTD + o] = acc[o] + bo[o];
    }
}

// ---------------------------------------------------------------------------
// Launch
// ---------------------------------------------------------------------------
extern "C" void kernel_launch(void* const* d_in, const int* in_sizes, int n_in,
                              void* d_out, int out_size)
{
    const float* x     = (const float*)d_in[0];
    const float* ln_g  = (const float*)d_in[1];
    const float* ln_b  = (const float*)d_in[2];
    const float* Wh    = (const float*)d_in[3];
    const float* bh    = (const float*)d_in[4];
    const float* Wqk   = (const float*)d_in[5];
    const float* bqk   = (const float*)d_in[6];
    const float* gamma = (const float*)d_in[7];
    const float* beta  = (const float*)d_in[8];
    const float* Wo    = (const float*)d_in[9];
    const float* bo    = (const float*)d_in[10];
    float* out = (float*)d_out;

    cudaFuncSetAttribute(proj_kernel<0>, cudaFuncAttributeMaxDynamicSharedMemorySize, GEMM_SMEM_BYTES);
    cudaFuncSetAttribute(proj_kernel<1>, cudaFuncAttributeMaxDynamicSharedMemorySize, GEMM_SMEM_BYTES);
    cudaFuncSetAttribute(attn_v_kernel,  cudaFuncAttributeMaxDynamicSharedMemorySize, GEMM_SMEM_BYTES);
    cudaFuncSetAttribute(attn_s_kernel,  cudaFuncAttributeMaxDynamicSharedMemorySize, ATTNS_SMEM_BYTES);

    ln_kernel<<<NROWS / 8, 256>>>(x, ln_g, ln_b);
    proj_kernel<0><<<dim3(HID2 / 128, NROWS / 128), 256, GEMM_SMEM_BYTES>>>(Wh, bh, nullptr, nullptr, HID2);
    proj_kernel<1><<<dim3(1, NROWS / 128), 256, GEMM_SMEM_BYTES>>>(Wqk, bqk, gamma, beta, QKD);
    attn_s_kernel<<<dim3(SEQ / 128, SEQ / 128, BATCH), 256, ATTNS_SMEM_BYTES>>>();
    attn_v_kernel<<<dim3(HIDN / 128, SEQ / 128, BATCH), 256, GEMM_SMEM_BYTES>>>();
    out_kernel<<<NROWS / 8, 256>>>(Wo, bo, out);
}